// round 9
// baseline (speedup 1.0000x reference)
#include <cuda_runtime.h>
#include <cuda_pipeline.h>
#include <math.h>
#include <stdint.h>

#define BB 256
#define UU 4096
#define VV 80
#define HH 1024
#define KK 10
#define NT 1024         // threads per block = 2 halves of 512
#define HT 512          // threads per half (one batch row each)
#define NGRP 6          // einsum u-groups (NGRP*VV = 480 <= HT)
#define UCAP 48         // prefetched c rows per b (covers typical ucut; fallback beyond)
#define ZSTART 64       // bulk zeros cover [ZSTART, UU]; end covers (ucut, ZSTART)

// Output layout (concatenated flattened, reference return order):
//   w               : BB*VV      floats (offset 0)
//   new_kappa       : BB*KK      floats (offset BB*VV)
//   phi_termination : BB*(UU+1)  floats (offset BB*VV + BB*KK)

#define HSYNC() asm volatile("bar.sync %0, %1;" :: "r"(s + 1), "r"(HT) : "memory")

__global__ __launch_bounds__(NT, 1) void softwindow_kernel(
    const float* __restrict__ x,        // [BB,1,HH]
    const float* __restrict__ c,        // [BB,UU,VV]
    const float* __restrict__ kappa,    // [BB,KK]
    const float* __restrict__ W,        // [3*KK,HH]
    const float* __restrict__ bias,     // [3*KK]
    const int*   __restrict__ lens32,   // [BB] int32 OR int64 viewed as int32 pairs
    float* __restrict__ out)
{
    __shared__ float c_sh[2][UCAP * VV];     // 30 KB
    __shared__ float phi_sh[2][UCAP];
    __shared__ float lin_sh[2][3 * KK];
    __shared__ float alpha_sh[2][KK];
    __shared__ float beta_sh[2][KK];
    __shared__ float nk_sh[2][KK];
    __shared__ float part_sh[2][NGRP][VV];   // 3.84 KB
    __shared__ int   ucut_sh[2];
    __shared__ int   or_sh[2][4];
    __shared__ int   is64_sh[2];

    const int tid_g = threadIdx.x;
    const int s     = tid_g >> 9;        // half id: 0 or 1
    const int tid   = tid_g & (HT - 1);  // local tid within half
    const int b     = 2 * blockIdx.x + s;
    const int warp  = tid >> 5;
    const int lane  = tid & 31;

    float* phit = out + (size_t)BB * VV + (size_t)BB * KK + (size_t)b * (UU + 1);

    // ---- dtype probe: int64 layout <=> all odd int32 words in [0,256) are zero ----
    if (tid < 128) {
        int v = lens32[2 * tid + 1];
        #pragma unroll
        for (int o = 16; o; o >>= 1) v |= __shfl_xor_sync(0xffffffffu, v, o);
        if (lane == 0) or_sh[s][warp] = v;
    }

    // ---- PHASE 1 (critical-path loads FIRST, nothing queued ahead of them):
    //      lin = x[b] @ W^T + bias : 30 dots, one warp per dot, straight from gmem ----
    const float4* xs = (const float4*)(x + (size_t)b * HH);
    for (int j = warp; j < 3 * KK; j += 16) {
        const float4* Wr = (const float4*)(W + (size_t)j * HH);
        float s0 = 0.f, s1 = 0.f, s2 = 0.f, s3 = 0.f;
        #pragma unroll
        for (int i = 0; i < HH / 4 / 32; i++) {        // 8 iterations, MLP ~16
            float4 wv = Wr[i * 32 + lane];
            float4 xv = xs[i * 32 + lane];
            s0 = fmaf(xv.x, wv.x, s0);
            s1 = fmaf(xv.y, wv.y, s1);
            s2 = fmaf(xv.z, wv.z, s2);
            s3 = fmaf(xv.w, wv.w, s3);
        }
        float sv = (s0 + s1) + (s2 + s3);
        #pragma unroll
        for (int o = 16; o; o >>= 1) sv += __shfl_xor_sync(0xffffffffu, sv, o);
        if (lane == 0) lin_sh[s][j] = sv + bias[j];
    }

    // ---- PHASE 2 (fire-and-forget, behind the critical loads):
    //      speculative prefetch of first UCAP rows of c[b] (contiguous 15 KB) ----
    {
        const float4* src = (const float4*)(c + (size_t)b * UU * VV);
        float4*       dst = (float4*)c_sh[s];
        for (int i = tid; i < UCAP * VV / 4; i += HT)
            __pipeline_memcpy_async(&dst[i], &src[i], 16);
        __pipeline_commit();
    }

    // ---- PHASE 3 (fire-and-forget stores): zeros for phi_termination[ZSTART..UU].
    //      phi overwrites [ZSTART, ucut] later if needed; named barriers order it. ----
    {
        int start = ZSTART;
        int mis = (int)((16u - ((uint32_t)(uintptr_t)(phit + start) & 15u)) & 15u) >> 2;
        if (tid < mis) phit[start + tid] = 0.f;
        start += mis;
        const int nv = (UU + 1 - start) >> 2;
        float4* p4 = (float4*)(phit + start);
        const float4 z = make_float4(0.f, 0.f, 0.f, 0.f);
        for (int i = tid; i < nv; i += HT) p4[i] = z;
        const int rem = start + nv * 4;
        if (tid < (UU + 1 - rem)) phit[rem + tid] = 0.f;
    }
    HSYNC();

    // ---- warp 0: alpha/beta/new_kappa + cutoff via warp max-reduce ----
    if (warp == 0) {
        float cut = 0.f;
        if (lane < KK) {
            float a  = expf(lin_sh[s][lane]);
            float be = expf(lin_sh[s][KK + lane]);
            float nk = kappa[(size_t)b * KK + lane] + expf(lin_sh[s][2 * KK + lane] - 3.9f);
            alpha_sh[s][lane] = a;
            beta_sh[s][lane]  = be;
            nk_sh[s][lane]    = nk;
            out[(size_t)BB * VV + (size_t)b * KK + lane] = nk;
            // beyond nk + sqrt(105/beta), every fp32 exp arg < -105 => exp == 0 exactly
            cut = nk + sqrtf(105.0f / be);
        }
        #pragma unroll
        for (int o = 16; o; o >>= 1) cut = fmaxf(cut, __shfl_xor_sync(0xffffffffu, cut, o));
        if (lane == 0) {
            int uc = (int)cut + 1;
            if (uc > UU) uc = UU;   // cap: correctness never depends on the cutoff
            if (uc < 0)  uc = 0;
            ucut_sh[s] = uc;
            is64_sh[s] = ((or_sh[s][0] | or_sh[s][1] | or_sh[s][2] | or_sh[s][3]) == 0);
        }
    }
    HSYNC();
    const int ucut = ucut_sh[s];

    // ---- active phi: u in [0, ucut] (typically ~25) ----
    if (tid <= ucut) {
        float a_r[KK], be_r[KK], nk_r[KK];
        #pragma unroll
        for (int k = 0; k < KK; k++) {
            a_r[k] = alpha_sh[s][k]; be_r[k] = beta_sh[s][k]; nk_r[k] = nk_sh[s][k];
        }
        for (int u = tid; u <= ucut; u += HT) {
            const float uf = (float)u;
            float val = 0.f;
            #pragma unroll
            for (int k = 0; k < KK; k++) {
                float d   = nk_r[k] - uf;
                float arg = -be_r[k] * d * d;
                val += a_r[k] * expf(arg);
            }
            phit[u] = val;
            if (u < UCAP) phi_sh[s][u] = val;
        }
    }
    __pipeline_wait_prior(0);   // c prefetch done (latency long since hidden)
    HSYNC();

    // ---- einsum: w[b,v] = sum_u phi[u]*c[b,u,v], u-parallel over NGRP groups ----
    const int len = is64_sh[s] ? lens32[2 * b] : lens32[b];
    int umax = ucut + 1;
    if (len < umax) umax = len;
    if (umax < 0)   umax = 0;
    if (umax > UU)  umax = UU;

    if (tid < NGRP * VV) {
        const int v = tid % VV;
        const int g = tid / VV;
        float acc = 0.f;
        int ufast = umax < UCAP ? umax : UCAP;
        for (int u = g; u < ufast; u += NGRP)
            acc = fmaf(phi_sh[s][u], c_sh[s][u * VV + v], acc);
        if (umax > UCAP) {
            // rare fallback: gmem c + recomputed phi
            int u0 = g;
            while (u0 < UCAP) u0 += NGRP;
            const float* cb = c + (size_t)b * UU * VV + v;
            for (int u = u0; u < umax; u += NGRP) {
                const float uf = (float)u;
                float ph = 0.f;
                #pragma unroll
                for (int k = 0; k < KK; k++) {
                    float d = nk_sh[s][k] - uf;
                    ph += alpha_sh[s][k] * expf(-beta_sh[s][k] * d * d);
                }
                acc = fmaf(ph, cb[(size_t)u * VV], acc);
            }
        }
        part_sh[s][g][v] = acc;
    }
    HSYNC();
    if (tid < VV) {
        float acc = 0.f;
        #pragma unroll
        for (int g = 0; g < NGRP; g++) acc += part_sh[s][g][tid];
        out[(size_t)b * VV + tid] = acc;
    }

    // ---- residual zeros: u in (ucut, ZSTART) only ----
    for (int u = ucut + 1 + tid; u < ZSTART; u += HT)
        phit[u] = 0.f;
}

extern "C" void kernel_launch(void* const* d_in, const int* in_sizes, int n_in,
                              void* d_out, int out_size) {
    const float* x     = (const float*)d_in[0];
    const float* c     = (const float*)d_in[1];
    const float* kappa = (const float*)d_in[2];
    const float* W     = (const float*)d_in[3];
    const float* bias  = (const float*)d_in[4];
    const int*   lens  = (const int*)d_in[5];
    float* out = (float*)d_out;

    softwindow_kernel<<<BB / 2, NT>>>(x, c, kappa, W, bias, lens, out);
}

// round 10
// speedup vs baseline: 1.0156x; 1.0156x over previous
#include <cuda_runtime.h>
#include <cuda_pipeline.h>
#include <math.h>
#include <stdint.h>

#define BB 256
#define UU 4096
#define VV 80
#define HH 1024
#define KK 10
#define NT 1024         // threads per block = 2 halves of 512
#define HT 512          // threads per half (one batch row each)
#define NGRP 6          // einsum u-groups (NGRP*VV = 480 <= HT)
#define UCAP 48         // prefetched c rows per b (covers typical ucut; fallback beyond)
#define ZSTART 64       // bulk zeros cover [ZSTART, UU]; end covers (ucut, ZSTART)

// Output layout (concatenated flattened, reference return order):
//   w               : BB*VV      floats (offset 0)
//   new_kappa       : BB*KK      floats (offset BB*VV)
//   phi_termination : BB*(UU+1)  floats (offset BB*VV + BB*KK)

#define HSYNC() asm volatile("bar.sync %0, %1;" :: "r"(s + 1), "r"(HT) : "memory")

__global__ __launch_bounds__(NT, 1) void softwindow_kernel(
    const float* __restrict__ x,        // [BB,1,HH]
    const float* __restrict__ c,        // [BB,UU,VV]
    const float* __restrict__ kappa,    // [BB,KK]
    const float* __restrict__ W,        // [3*KK,HH]
    const float* __restrict__ bias,     // [3*KK]
    const int*   __restrict__ lens32,   // [BB] int32 OR int64 viewed as int32 pairs
    float* __restrict__ out)
{
    __shared__ float c_sh[2][UCAP * VV];     // 30 KB
    __shared__ float phi_sh[2][UCAP];
    __shared__ float lin_sh[2][3 * KK];
    __shared__ float alpha_sh[2][KK];
    __shared__ float beta_sh[2][KK];
    __shared__ float nk_sh[2][KK];
    __shared__ float part_sh[2][NGRP][VV];   // 3.84 KB
    __shared__ int   ucut_sh[2];
    __shared__ int   or_sh[2][4];
    __shared__ int   is64_sh[2];

    const int tid_g = threadIdx.x;
    const int s     = tid_g >> 9;        // half id: 0 or 1
    const int tid   = tid_g & (HT - 1);  // local tid within half
    const int b     = 2 * blockIdx.x + s;
    const int warp  = tid >> 5;
    const int lane  = tid & 31;

    float* phit = out + (size_t)BB * VV + (size_t)BB * KK + (size_t)b * (UU + 1);

    // ---- hoisted scalar loads (addresses data-independent; issue at entry) ----
    float kap_r = 0.f;
    if (warp == 0 && lane < KK) kap_r = kappa[(size_t)b * KK + lane];
    const int len32_r = lens32[b];        // candidate if dtype == int32
    const int len64_r = lens32[2 * b];    // candidate if dtype == int64 (low word)

    // ---- dtype probe: int64 layout <=> all odd int32 words in [0,256) are zero ----
    if (tid < 128) {
        int v = lens32[2 * tid + 1];
        #pragma unroll
        for (int o = 16; o; o >>= 1) v |= __shfl_xor_sync(0xffffffffu, v, o);
        if (lane == 0) or_sh[s][warp] = v;
    }

    // ---- PHASE 1 (critical-path loads FIRST): lin = x[b] @ W^T + bias.
    //      30 dots over 16 warps, peeled 2-per-warp with concurrent accumulators ----
    {
        const float4* xs = (const float4*)(x + (size_t)b * HH);
        const int j0 = warp;
        const int j1 = warp + 16;
        const bool h1 = (j1 < 3 * KK);                 // warps 14,15 have no j1
        const float4* W0 = (const float4*)(W + (size_t)j0 * HH);
        const float4* W1 = (const float4*)(W + (size_t)(h1 ? j1 : j0) * HH);
        float s0 = 0.f, s1 = 0.f, s2 = 0.f, s3 = 0.f;
        float t0 = 0.f, t1 = 0.f, t2 = 0.f, t3 = 0.f;
        #pragma unroll
        for (int i = 0; i < HH / 4 / 32; i++) {        // 8 iterations, MLP ~24
            float4 xv = xs[i * 32 + lane];
            float4 w0 = W0[i * 32 + lane];
            float4 w1 = W1[i * 32 + lane];
            s0 = fmaf(xv.x, w0.x, s0);  t0 = fmaf(xv.x, w1.x, t0);
            s1 = fmaf(xv.y, w0.y, s1);  t1 = fmaf(xv.y, w1.y, t1);
            s2 = fmaf(xv.z, w0.z, s2);  t2 = fmaf(xv.z, w1.z, t2);
            s3 = fmaf(xv.w, w0.w, s3);  t3 = fmaf(xv.w, w1.w, t3);
        }
        float sv = (s0 + s1) + (s2 + s3);
        float tv = (t0 + t1) + (t2 + t3);
        #pragma unroll
        for (int o = 16; o; o >>= 1) {
            sv += __shfl_xor_sync(0xffffffffu, sv, o);
            tv += __shfl_xor_sync(0xffffffffu, tv, o);
        }
        if (lane == 0) {
            lin_sh[s][j0] = sv + bias[j0];
            if (h1) lin_sh[s][j1] = tv + bias[j1];
        }
    }

    // ---- PHASE 2 (fire-and-forget): prefetch first UCAP rows of c[b] (15 KB) ----
    {
        const float4* src = (const float4*)(c + (size_t)b * UU * VV);
        float4*       dst = (float4*)c_sh[s];
        for (int i = tid; i < UCAP * VV / 4; i += HT)
            __pipeline_memcpy_async(&dst[i], &src[i], 16);
        __pipeline_commit();
    }

    // ---- PHASE 3 (fire-and-forget stores): zeros for phi_termination[ZSTART..UU].
    //      phi overwrites [ZSTART, ucut] later if needed; named barriers order it. ----
    {
        int start = ZSTART;
        int mis = (int)((16u - ((uint32_t)(uintptr_t)(phit + start) & 15u)) & 15u) >> 2;
        if (tid < mis) phit[start + tid] = 0.f;
        start += mis;
        const int nv = (UU + 1 - start) >> 2;
        float4* p4 = (float4*)(phit + start);
        const float4 z = make_float4(0.f, 0.f, 0.f, 0.f);
        for (int i = tid; i < nv; i += HT) p4[i] = z;
        const int rem = start + nv * 4;
        if (tid < (UU + 1 - rem)) phit[rem + tid] = 0.f;
    }
    HSYNC();

    // ---- warp 0: alpha/beta/new_kappa + cutoff via warp max-reduce ----
    if (warp == 0) {
        float cut = 0.f;
        if (lane < KK) {
            float a  = expf(lin_sh[s][lane]);
            float be = expf(lin_sh[s][KK + lane]);
            float nk = kap_r + expf(lin_sh[s][2 * KK + lane] - 3.9f);
            alpha_sh[s][lane] = a;
            beta_sh[s][lane]  = be;
            nk_sh[s][lane]    = nk;
            out[(size_t)BB * VV + (size_t)b * KK + lane] = nk;
            // beyond nk + sqrt(105/beta), every fp32 exp arg < -105 => exp == 0 exactly
            cut = nk + sqrtf(105.0f / be);
        }
        #pragma unroll
        for (int o = 16; o; o >>= 1) cut = fmaxf(cut, __shfl_xor_sync(0xffffffffu, cut, o));
        if (lane == 0) {
            int uc = (int)cut + 1;
            if (uc > UU) uc = UU;   // cap: correctness never depends on the cutoff
            if (uc < 0)  uc = 0;
            ucut_sh[s] = uc;
            is64_sh[s] = ((or_sh[s][0] | or_sh[s][1] | or_sh[s][2] | or_sh[s][3]) == 0);
        }
    }
    HSYNC();
    const int ucut = ucut_sh[s];

    // ---- active phi: u in [0, ucut] (typically ~25) ----
    if (tid <= ucut) {
        float a_r[KK], be_r[KK], nk_r[KK];
        #pragma unroll
        for (int k = 0; k < KK; k++) {
            a_r[k] = alpha_sh[s][k]; be_r[k] = beta_sh[s][k]; nk_r[k] = nk_sh[s][k];
        }
        for (int u = tid; u <= ucut; u += HT) {
            const float uf = (float)u;
            float val = 0.f;
            #pragma unroll
            for (int k = 0; k < KK; k++) {
                float d   = nk_r[k] - uf;
                float arg = -be_r[k] * d * d;
                val += a_r[k] * expf(arg);
            }
            phit[u] = val;
            if (u < UCAP) phi_sh[s][u] = val;
        }
    }
    __pipeline_wait_prior(0);   // c prefetch done (latency long since hidden)
    HSYNC();

    // ---- einsum: w[b,v] = sum_u phi[u]*c[b,u,v], u-parallel over NGRP groups ----
    const int len = is64_sh[s] ? len64_r : len32_r;
    int umax = ucut + 1;
    if (len < umax) umax = len;
    if (umax < 0)   umax = 0;
    if (umax > UU)  umax = UU;

    if (tid < NGRP * VV) {
        const int v = tid % VV;
        const int g = tid / VV;
        float acc = 0.f;
        int ufast = umax < UCAP ? umax : UCAP;
        for (int u = g; u < ufast; u += NGRP)
            acc = fmaf(phi_sh[s][u], c_sh[s][u * VV + v], acc);
        if (umax > UCAP) {
            // rare fallback: gmem c + recomputed phi
            int u0 = g;
            while (u0 < UCAP) u0 += NGRP;
            const float* cb = c + (size_t)b * UU * VV + v;
            for (int u = u0; u < umax; u += NGRP) {
                const float uf = (float)u;
                float ph = 0.f;
                #pragma unroll
                for (int k = 0; k < KK; k++) {
                    float d = nk_sh[s][k] - uf;
                    ph += alpha_sh[s][k] * expf(-beta_sh[s][k] * d * d);
                }
                acc = fmaf(ph, cb[(size_t)u * VV], acc);
            }
        }
        part_sh[s][g][v] = acc;
    }
    HSYNC();
    if (tid < VV) {
        float acc = 0.f;
        #pragma unroll
        for (int g = 0; g < NGRP; g++) acc += part_sh[s][g][tid];
        out[(size_t)b * VV + tid] = acc;
    }

    // ---- residual zeros: u in (ucut, ZSTART) only ----
    for (int u = ucut + 1 + tid; u < ZSTART; u += HT)
        phit[u] = 0.f;
}

extern "C" void kernel_launch(void* const* d_in, const int* in_sizes, int n_in,
                              void* d_out, int out_size) {
    const float* x     = (const float*)d_in[0];
    const float* c     = (const float*)d_in[1];
    const float* kappa = (const float*)d_in[2];
    const float* W     = (const float*)d_in[3];
    const float* bias  = (const float*)d_in[4];
    const int*   lens  = (const int*)d_in[5];
    float* out = (float*)d_out;

    softwindow_kernel<<<BB / 2, NT>>>(x, c, kappa, W, bias, lens, out);
}

// round 11
// speedup vs baseline: 1.0188x; 1.0031x over previous
#include <cuda_runtime.h>
#include <cuda_pipeline.h>
#include <math.h>
#include <stdint.h>

#define BB 256
#define UU 4096
#define VV 80
#define HH 1024
#define KK 10
#define NT 1024         // threads per block = 2 halves of 512
#define HT 512          // threads per half (one batch row each)
#define NGRP 6          // einsum u-groups (NGRP*VV = 480 <= HT)
#define UCAP 48         // prefetched c rows per b (covers typical ucut; fallback beyond)
#define ZSTART 64       // bulk zeros cover [ZSTART, UU]; phi phase covers [0, ZSTART)

// Output layout (concatenated flattened, reference return order):
//   w               : BB*VV      floats (offset 0)
//   new_kappa       : BB*KK      floats (offset BB*VV)
//   phi_termination : BB*(UU+1)  floats (offset BB*VV + BB*KK)

#define HSYNC() asm volatile("bar.sync %0, %1;" :: "r"(s + 1), "r"(HT) : "memory")

__global__ __launch_bounds__(NT, 1) void softwindow_kernel(
    const float* __restrict__ x,        // [BB,1,HH]
    const float* __restrict__ c,        // [BB,UU,VV]
    const float* __restrict__ kappa,    // [BB,KK]
    const float* __restrict__ W,        // [3*KK,HH]
    const float* __restrict__ bias,     // [3*KK]
    const int*   __restrict__ lens32,   // [BB] int32 OR int64 viewed as int32 pairs
    float* __restrict__ out)
{
    __shared__ float c_sh[2][UCAP * VV];     // 30 KB
    __shared__ float phi_sh[2][UCAP];
    __shared__ float lin_sh[2][3 * KK];
    __shared__ float alpha_sh[2][KK];
    __shared__ float beta_sh[2][KK];
    __shared__ float nk_sh[2][KK];
    __shared__ float part_sh[2][NGRP][VV];   // 3.84 KB
    __shared__ int   ucut_sh[2];
    __shared__ int   or_sh[2][4];
    __shared__ int   is64_sh[2];

    const int tid_g = threadIdx.x;
    const int s     = tid_g >> 9;        // half id: 0 or 1
    const int tid   = tid_g & (HT - 1);  // local tid within half
    const int b     = 2 * blockIdx.x + s;
    const int warp  = tid >> 5;
    const int lane  = tid & 31;

    float* phit = out + (size_t)BB * VV + (size_t)BB * KK + (size_t)b * (UU + 1);

    // ---- hoisted scalar loads (addresses data-independent; issue at entry) ----
    float kap_r = 0.f;
    if (warp == 0 && lane < KK) kap_r = kappa[(size_t)b * KK + lane];
    const int len32_r = lens32[b];        // candidate if dtype == int32
    const int len64_r = lens32[2 * b];    // candidate if dtype == int64 (low word)

    // ---- dtype probe: int64 layout <=> all odd int32 words in [0,256) are zero ----
    if (tid < 128) {
        int v = lens32[2 * tid + 1];
        #pragma unroll
        for (int o = 16; o; o >>= 1) v |= __shfl_xor_sync(0xffffffffu, v, o);
        if (lane == 0) or_sh[s][warp] = v;
    }

    // ---- PHASE 1 (critical-path loads FIRST): lin = x[b] @ W^T + bias.
    //      30 dots over 16 warps, peeled 2-per-warp with concurrent accumulators ----
    {
        const float4* xs = (const float4*)(x + (size_t)b * HH);
        const int j0 = warp;
        const int j1 = warp + 16;
        const bool h1 = (j1 < 3 * KK);                 // warps 14,15 have no j1
        const float4* W0 = (const float4*)(W + (size_t)j0 * HH);
        const float4* W1 = (const float4*)(W + (size_t)(h1 ? j1 : j0) * HH);
        float s0 = 0.f, s1 = 0.f, s2 = 0.f, s3 = 0.f;
        float t0 = 0.f, t1 = 0.f, t2 = 0.f, t3 = 0.f;
        #pragma unroll
        for (int i = 0; i < HH / 4 / 32; i++) {        // 8 iterations, MLP ~24
            float4 xv = xs[i * 32 + lane];
            float4 w0 = W0[i * 32 + lane];
            float4 w1 = W1[i * 32 + lane];
            s0 = fmaf(xv.x, w0.x, s0);  t0 = fmaf(xv.x, w1.x, t0);
            s1 = fmaf(xv.y, w0.y, s1);  t1 = fmaf(xv.y, w1.y, t1);
            s2 = fmaf(xv.z, w0.z, s2);  t2 = fmaf(xv.z, w1.z, t2);
            s3 = fmaf(xv.w, w0.w, s3);  t3 = fmaf(xv.w, w1.w, t3);
        }
        float sv = (s0 + s1) + (s2 + s3);
        float tv = (t0 + t1) + (t2 + t3);
        #pragma unroll
        for (int o = 16; o; o >>= 1) {
            sv += __shfl_xor_sync(0xffffffffu, sv, o);
            tv += __shfl_xor_sync(0xffffffffu, tv, o);
        }
        if (lane == 0) {
            lin_sh[s][j0] = sv + bias[j0];
            if (h1) lin_sh[s][j1] = tv + bias[j1];
        }
    }

    // ---- PHASE 2 (fire-and-forget): prefetch first UCAP rows of c[b] (15 KB) ----
    {
        const float4* src = (const float4*)(c + (size_t)b * UU * VV);
        float4*       dst = (float4*)c_sh[s];
        for (int i = tid; i < UCAP * VV / 4; i += HT)
            __pipeline_memcpy_async(&dst[i], &src[i], 16);
        __pipeline_commit();
    }

    // ---- PHASE 3 (fire-and-forget streaming stores): zeros for [ZSTART..UU].
    //      phi overwrites [ZSTART, ucut] later if needed; named barriers order it. ----
    {
        int start = ZSTART;
        int mis = (int)((16u - ((uint32_t)(uintptr_t)(phit + start) & 15u)) & 15u) >> 2;
        if (tid < mis) phit[start + tid] = 0.f;
        start += mis;
        const int nv = (UU + 1 - start) >> 2;
        float4* p4 = (float4*)(phit + start);
        const float4 z = make_float4(0.f, 0.f, 0.f, 0.f);
        for (int i = tid; i < nv; i += HT) __stcg(&p4[i], z);
        const int rem = start + nv * 4;
        if (tid < (UU + 1 - rem)) phit[rem + tid] = 0.f;
    }
    HSYNC();

    // ---- warp 0: alpha/beta/new_kappa + cutoff via warp max-reduce ----
    if (warp == 0) {
        float cut = 0.f;
        if (lane < KK) {
            float a  = expf(lin_sh[s][lane]);
            float be = expf(lin_sh[s][KK + lane]);
            float nk = kap_r + expf(lin_sh[s][2 * KK + lane] - 3.9f);
            alpha_sh[s][lane] = a;
            beta_sh[s][lane]  = be;
            nk_sh[s][lane]    = nk;
            out[(size_t)BB * VV + (size_t)b * KK + lane] = nk;
            // beyond nk + sqrt(105/beta), every fp32 exp arg < -105 => exp == 0 exactly
            cut = nk + sqrtf(105.0f / be);
        }
        #pragma unroll
        for (int o = 16; o; o >>= 1) cut = fmaxf(cut, __shfl_xor_sync(0xffffffffu, cut, o));
        if (lane == 0) {
            int uc = (int)cut + 1;
            if (uc > UU) uc = UU;   // cap: correctness never depends on the cutoff
            if (uc < 0)  uc = 0;
            ucut_sh[s] = uc;
            is64_sh[s] = ((or_sh[s][0] | or_sh[s][1] | or_sh[s][2] | or_sh[s][3]) == 0);
        }
    }
    HSYNC();
    const int ucut = ucut_sh[s];

    // ---- phi phase covers [0, max(ucut, ZSTART-1)]: computed vals for u <= ucut,
    //      literal zeros for (ucut, ZSTART) — no residual zero loop at kernel end ----
    {
        const int utop = (ucut > ZSTART - 1) ? ucut : (ZSTART - 1);
        if (tid <= utop) {
            float a_r[KK], be_r[KK], nk_r[KK];
            #pragma unroll
            for (int k = 0; k < KK; k++) {
                a_r[k] = alpha_sh[s][k]; be_r[k] = beta_sh[s][k]; nk_r[k] = nk_sh[s][k];
            }
            for (int u = tid; u <= utop; u += HT) {
                float val = 0.f;
                if (u <= ucut) {
                    const float uf = (float)u;
                    #pragma unroll
                    for (int k = 0; k < KK; k++) {
                        float d   = nk_r[k] - uf;
                        float arg = -be_r[k] * d * d;
                        val += a_r[k] * expf(arg);
                    }
                }
                phit[u] = val;
                if (u < UCAP) phi_sh[s][u] = val;
            }
        }
    }
    __pipeline_wait_prior(0);   // c prefetch done (latency long since hidden)
    HSYNC();

    // ---- einsum: w[b,v] = sum_u phi[u]*c[b,u,v], u-parallel over NGRP groups ----
    const int len = is64_sh[s] ? len64_r : len32_r;
    int umax = ucut + 1;
    if (len < umax) umax = len;
    if (umax < 0)   umax = 0;
    if (umax > UU)  umax = UU;

    if (tid < NGRP * VV) {
        const int v = tid % VV;
        const int g = tid / VV;
        float acc = 0.f;
        int ufast = umax < UCAP ? umax : UCAP;
        for (int u = g; u < ufast; u += NGRP)
            acc = fmaf(phi_sh[s][u], c_sh[s][u * VV + v], acc);
        if (umax > UCAP) {
            // rare fallback: gmem c + recomputed phi
            int u0 = g;
            while (u0 < UCAP) u0 += NGRP;
            const float* cb = c + (size_t)b * UU * VV + v;
            for (int u = u0; u < umax; u += NGRP) {
                const float uf = (float)u;
                float ph = 0.f;
                #pragma unroll
                for (int k = 0; k < KK; k++) {
                    float d = nk_sh[s][k] - uf;
                    ph += alpha_sh[s][k] * expf(-beta_sh[s][k] * d * d);
                }
                acc = fmaf(ph, cb[(size_t)u * VV], acc);
            }
        }
        part_sh[s][g][v] = acc;
    }
    HSYNC();
    if (tid < VV) {
        float acc = 0.f;
        #pragma unroll
        for (int g = 0; g < NGRP; g++) acc += part_sh[s][g][tid];
        out[(size_t)b * VV + tid] = acc;
    }
}

extern "C" void kernel_launch(void* const* d_in, const int* in_sizes, int n_in,
                              void* d_out, int out_size) {
    const float* x     = (const float*)d_in[0];
    const float* c     = (const float*)d_in[1];
    const float* kappa = (const float*)d_in[2];
    const float* W     = (const float*)d_in[3];
    const float* bias  = (const float*)d_in[4];
    const int*   lens  = (const int*)d_in[5];
    float* out = (float*)d_out;

    softwindow_kernel<<<BB / 2, NT>>>(x, c, kappa, W, bias, lens, out);
}

// round 12
// speedup vs baseline: 1.1285x; 1.1076x over previous
#include <cuda_runtime.h>
#include <cuda_pipeline.h>
#include <math.h>
#include <stdint.h>

#define BB 256
#define UU 4096
#define VV 80
#define HH 1024
#define KK 10
#define NT 1024         // threads per block = 2 halves of 512
#define HT 512          // threads per half (one batch row each)
#define NGRP 6          // einsum u-groups (NGRP*VV = 480 <= HT)
#define UCAP 48         // prefetched c rows per b (covers typical ucut; fallback beyond)
#define ZSTART 64       // bulk zeros cover [ZSTART, UU]; phi phase covers [0, ZSTART)

// Output layout (concatenated flattened, reference return order):
//   w               : BB*VV      floats (offset 0)
//   new_kappa       : BB*KK      floats (offset BB*VV)
//   phi_termination : BB*(UU+1)  floats (offset BB*VV + BB*KK)

#define HSYNC() asm volatile("bar.sync %0, %1;" :: "r"(s + 1), "r"(HT) : "memory")

__global__ __launch_bounds__(NT, 1) void softwindow_kernel(
    const float* __restrict__ x,        // [BB,1,HH]
    const float* __restrict__ c,        // [BB,UU,VV]
    const float* __restrict__ kappa,    // [BB,KK]
    const float* __restrict__ W,        // [3*KK,HH]
    const float* __restrict__ bias,     // [3*KK]
    const int*   __restrict__ lens32,   // [BB] int32 OR int64 viewed as int32 pairs
    float* __restrict__ out)
{
    __shared__ float c_sh[2][UCAP * VV];     // 30 KB
    __shared__ float phi_sh[2][UCAP];
    __shared__ float lin_sh[2][3 * KK];
    __shared__ float alpha_sh[2][KK];
    __shared__ float beta_sh[2][KK];
    __shared__ float nk_sh[2][KK];
    __shared__ float part_sh[2][NGRP][VV];   // 3.84 KB
    __shared__ int   ucut_sh[2];
    __shared__ int   or_sh[2][4];
    __shared__ int   is64_sh[2];

    const int tid_g = threadIdx.x;
    const int s     = tid_g >> 9;        // half id: 0 or 1
    const int tid   = tid_g & (HT - 1);  // local tid within half
    const int b     = 2 * blockIdx.x + s;
    const int warp  = tid >> 5;
    const int lane  = tid & 31;

    float* phit = out + (size_t)BB * VV + (size_t)BB * KK + (size_t)b * (UU + 1);

    // ---- hoisted scalar loads (addresses data-independent; issue at entry) ----
    float kap_r = 0.f;
    if (warp == 0 && lane < KK) kap_r = kappa[(size_t)b * KK + lane];
    const int len32_r = lens32[b];        // candidate if dtype == int32
    const int len64_r = lens32[2 * b];    // candidate if dtype == int64 (low word)

    // ---- dtype probe: int64 layout <=> all odd int32 words in [0,256) are zero ----
    if (tid < 128) {
        int v = lens32[2 * tid + 1];
        #pragma unroll
        for (int o = 16; o; o >>= 1) v |= __shfl_xor_sync(0xffffffffu, v, o);
        if (lane == 0) or_sh[s][warp] = v;
    }

    // ---- PHASE 1 (critical-path loads FIRST): lin = x[b] @ W^T + bias.
    //      30 dots over 16 warps, peeled 2-per-warp with concurrent accumulators ----
    {
        const float4* xs = (const float4*)(x + (size_t)b * HH);
        const int j0 = warp;
        const int j1 = warp + 16;
        const bool h1 = (j1 < 3 * KK);                 // warps 14,15 have no j1
        const float4* W0 = (const float4*)(W + (size_t)j0 * HH);
        const float4* W1 = (const float4*)(W + (size_t)(h1 ? j1 : j0) * HH);
        float s0 = 0.f, s1 = 0.f, s2 = 0.f, s3 = 0.f;
        float t0 = 0.f, t1 = 0.f, t2 = 0.f, t3 = 0.f;
        #pragma unroll
        for (int i = 0; i < HH / 4 / 32; i++) {        // 8 iterations, MLP ~24
            float4 xv = xs[i * 32 + lane];
            float4 w0 = W0[i * 32 + lane];
            float4 w1 = W1[i * 32 + lane];
            s0 = fmaf(xv.x, w0.x, s0);  t0 = fmaf(xv.x, w1.x, t0);
            s1 = fmaf(xv.y, w0.y, s1);  t1 = fmaf(xv.y, w1.y, t1);
            s2 = fmaf(xv.z, w0.z, s2);  t2 = fmaf(xv.z, w1.z, t2);
            s3 = fmaf(xv.w, w0.w, s3);  t3 = fmaf(xv.w, w1.w, t3);
        }
        float sv = (s0 + s1) + (s2 + s3);
        float tv = (t0 + t1) + (t2 + t3);
        #pragma unroll
        for (int o = 16; o; o >>= 1) {
            sv += __shfl_xor_sync(0xffffffffu, sv, o);
            tv += __shfl_xor_sync(0xffffffffu, tv, o);
        }
        if (lane == 0) {
            lin_sh[s][j0] = sv + bias[j0];
            if (h1) lin_sh[s][j1] = tv + bias[j1];
        }
    }

    // ---- PHASE 2 (fire-and-forget): prefetch first UCAP rows of c[b] (15 KB) ----
    {
        const float4* src = (const float4*)(c + (size_t)b * UU * VV);
        float4*       dst = (float4*)c_sh[s];
        for (int i = tid; i < UCAP * VV / 4; i += HT)
            __pipeline_memcpy_async(&dst[i], &src[i], 16);
        __pipeline_commit();
    }

    // ---- PHASE 3 (fire-and-forget stores): zeros for phi_termination[ZSTART..UU].
    //      phi overwrites [ZSTART, ucut] later if needed; named barriers order it. ----
    {
        int start = ZSTART;
        int mis = (int)((16u - ((uint32_t)(uintptr_t)(phit + start) & 15u)) & 15u) >> 2;
        if (tid < mis) phit[start + tid] = 0.f;
        start += mis;
        const int nv = (UU + 1 - start) >> 2;
        float4* p4 = (float4*)(phit + start);
        const float4 z = make_float4(0.f, 0.f, 0.f, 0.f);
        for (int i = tid; i < nv; i += HT) p4[i] = z;
        const int rem = start + nv * 4;
        if (tid < (UU + 1 - rem)) phit[rem + tid] = 0.f;
    }
    HSYNC();

    // ---- warp 0: alpha/beta/new_kappa + cutoff via warp max-reduce ----
    if (warp == 0) {
        float cut = 0.f;
        if (lane < KK) {
            float a  = expf(lin_sh[s][lane]);
            float be = expf(lin_sh[s][KK + lane]);
            float nk = kap_r + expf(lin_sh[s][2 * KK + lane] - 3.9f);
            alpha_sh[s][lane] = a;
            beta_sh[s][lane]  = be;
            nk_sh[s][lane]    = nk;
            out[(size_t)BB * VV + (size_t)b * KK + lane] = nk;
            // beyond nk + sqrt(105/beta), every fp32 exp arg < -105 => exp == 0 exactly
            cut = nk + sqrtf(105.0f / be);
        }
        #pragma unroll
        for (int o = 16; o; o >>= 1) cut = fmaxf(cut, __shfl_xor_sync(0xffffffffu, cut, o));
        if (lane == 0) {
            int uc = (int)cut + 1;
            if (uc > UU) uc = UU;   // cap: correctness never depends on the cutoff
            if (uc < 0)  uc = 0;
            ucut_sh[s] = uc;
            is64_sh[s] = ((or_sh[s][0] | or_sh[s][1] | or_sh[s][2] | or_sh[s][3]) == 0);
        }
    }
    HSYNC();
    const int ucut = ucut_sh[s];

    // ---- phi phase covers [0, max(ucut, ZSTART-1)]: computed vals for u <= ucut,
    //      literal zeros for (ucut, ZSTART) — no residual zero loop at kernel end ----
    {
        const int utop = (ucut > ZSTART - 1) ? ucut : (ZSTART - 1);
        if (tid <= utop) {
            float a_r[KK], be_r[KK], nk_r[KK];
            #pragma unroll
            for (int k = 0; k < KK; k++) {
                a_r[k] = alpha_sh[s][k]; be_r[k] = beta_sh[s][k]; nk_r[k] = nk_sh[s][k];
            }
            for (int u = tid; u <= utop; u += HT) {
                float val = 0.f;
                if (u <= ucut) {
                    const float uf = (float)u;
                    #pragma unroll
                    for (int k = 0; k < KK; k++) {
                        float d   = nk_r[k] - uf;
                        float arg = -be_r[k] * d * d;
                        val += a_r[k] * __expf(arg);   // fast exp: ~1e-6 rel, << 1e-3
                    }
                }
                phit[u] = val;
                if (u < UCAP) phi_sh[s][u] = val;
            }
        }
    }
    __pipeline_wait_prior(0);   // c prefetch done (latency long since hidden)
    HSYNC();

    // ---- einsum: w[b,v] = sum_u phi[u]*c[b,u,v], u-parallel over NGRP groups ----
    const int len = is64_sh[s] ? len64_r : len32_r;
    int umax = ucut + 1;
    if (len < umax) umax = len;
    if (umax < 0)   umax = 0;
    if (umax > UU)  umax = UU;

    if (tid < NGRP * VV) {
        const int v = tid % VV;
        const int g = tid / VV;
        float acc = 0.f;
        int ufast = umax < UCAP ? umax : UCAP;
        for (int u = g; u < ufast; u += NGRP)
            acc = fmaf(phi_sh[s][u], c_sh[s][u * VV + v], acc);
        if (umax > UCAP) {
            // rare fallback: gmem c + recomputed phi
            int u0 = g;
            while (u0 < UCAP) u0 += NGRP;
            const float* cb = c + (size_t)b * UU * VV + v;
            for (int u = u0; u < umax; u += NGRP) {
                const float uf = (float)u;
                float ph = 0.f;
                #pragma unroll
                for (int k = 0; k < KK; k++) {
                    float d = nk_sh[s][k] - uf;
                    ph += alpha_sh[s][k] * __expf(-beta_sh[s][k] * d * d);
                }
                acc = fmaf(ph, cb[(size_t)u * VV], acc);
            }
        }
        part_sh[s][g][v] = acc;
    }
    HSYNC();
    if (tid < VV) {
        float acc = 0.f;
        #pragma unroll
        for (int g = 0; g < NGRP; g++) acc += part_sh[s][g][tid];
        out[(size_t)b * VV + tid] = acc;
    }
}

extern "C" void kernel_launch(void* const* d_in, const int* in_sizes, int n_in,
                              void* d_out, int out_size) {
    const float* x     = (const float*)d_in[0];
    const float* c     = (const float*)d_in[1];
    const float* kappa = (const float*)d_in[2];
    const float* W     = (const float*)d_in[3];
    const float* bias  = (const float*)d_in[4];
    const int*   lens  = (const int*)d_in[5];
    float* out = (float*)d_out;

    softwindow_kernel<<<BB / 2, NT>>>(x, c, kappa, W, bias, lens, out);
}